// round 10
// baseline (speedup 1.0000x reference)
#include <cuda_runtime.h>
#include <cuda_bf16.h>
#include <cstdint>
#include <math.h>

// ---------------------------------------------------------------------------
//   q (64,128,512)  kv (64,512,256)  Wq (512,1024)  Wkv (256,2048)
//   Wo (1024,512)  bo (512)  out (64,128,512)
// HMMA everywhere, fp32 via bf16 hi/lo 3-split. Persistent-CTA GEMM12 and
// attention; smem-tiled prep transposes; smem-staged epilogues.
// ---------------------------------------------------------------------------

#define B_ASSETS 64
#define I_LAT    128
#define J_WIN    512
#define QD       512
#define KVD      256
#define HID      1024
#define NH       16
#define HD       64

#define PERSIST_CTAS 296

// ------------------------- scratch (no cudaMalloc) -------------------------
__device__ __nv_bfloat16  g_qhi  [8192u  * 512u],  g_qlo  [8192u  * 512u];
__device__ __nv_bfloat16  g_kvhi [32768u * 256u],  g_kvlo [32768u * 256u];
__device__ __nv_bfloat16  g_qphi [8192u  * 1024u], g_qplo [8192u  * 1024u];
__device__ __nv_bfloat16  g_kvphi[32768u * 2048u], g_kvplo[32768u * 2048u];
__device__ __nv_bfloat16  g_athi [8192u  * 1024u], g_atlo [8192u  * 1024u];
__device__ __nv_bfloat16  g_wqthi [1024u * 512u],  g_wqtlo [1024u * 512u];
__device__ __nv_bfloat16  g_wkvthi[2048u * 256u],  g_wkvtlo[2048u * 256u];
__device__ __nv_bfloat16  g_wothi [512u * 1024u],  g_wotlo [512u * 1024u];

// ------------------------------ PTX helpers --------------------------------
__device__ __forceinline__ uint32_t smem_u32(const void* p) {
    uint32_t a;
    asm("{ .reg .u64 t; cvta.to.shared.u64 t, %1; cvt.u32.u64 %0, t; }"
        : "=r"(a) : "l"(p));
    return a;
}
__device__ __forceinline__ void cp16(uint32_t dst, const void* src) {
    asm volatile("cp.async.cg.shared.global [%0], [%1], 16;"
                 :: "r"(dst), "l"(src));
}
#define CP_COMMIT() asm volatile("cp.async.commit_group;" ::: "memory")
#define CP_WAIT(n)  asm volatile("cp.async.wait_group %0;" :: "n"(n) : "memory")

__device__ __forceinline__ void ldsm_x4(uint32_t (&r)[4], uint32_t addr) {
    asm volatile("ldmatrix.sync.aligned.m8n8.x4.shared.b16 {%0,%1,%2,%3}, [%4];"
                 : "=r"(r[0]), "=r"(r[1]), "=r"(r[2]), "=r"(r[3]) : "r"(addr));
}
__device__ __forceinline__ void ldsm_x4t(uint32_t (&r)[4], uint32_t addr) {
    asm volatile("ldmatrix.sync.aligned.m8n8.x4.trans.shared.b16 {%0,%1,%2,%3}, [%4];"
                 : "=r"(r[0]), "=r"(r[1]), "=r"(r[2]), "=r"(r[3]) : "r"(addr));
}
__device__ __forceinline__ void mma_bf16(float (&d)[4],
                                         const uint32_t (&a)[4],
                                         uint32_t b0, uint32_t b1) {
    asm volatile(
        "mma.sync.aligned.m16n8k16.row.col.f32.bf16.bf16.f32 "
        "{%0,%1,%2,%3}, {%4,%5,%6,%7}, {%8,%9}, {%0,%1,%2,%3};"
        : "+f"(d[0]), "+f"(d[1]), "+f"(d[2]), "+f"(d[3])
        : "r"(a[0]), "r"(a[1]), "r"(a[2]), "r"(a[3]), "r"(b0), "r"(b1));
}
__device__ __forceinline__ uint32_t pack_bf16(float lo, float hi) {
    __nv_bfloat162 h = __floats2bfloat162_rn(lo, hi);
    return *reinterpret_cast<uint32_t*>(&h);
}
__device__ __forceinline__ uint32_t swz(uint32_t b) {
    return b ^ ((b >> 3) & 0x70);
}

// ---------------------------------------------------------------------------
// GEMM machinery: CTA 128x128 (128 threads, 4 warps, 2x2 of 64x64 tiles),
// BK=32, 3-stage cp.async, swizzled smem.
// ---------------------------------------------------------------------------
#define BM 128
#define BN 128
#define BK 32
#define ARR_B 8192u
#define STG_B 32768u
#define GEMM_SMEM (3 * 32768)
#define EPIT   272u
#define EARR   34816u
#define EPIT32 528u

__device__ __forceinline__ void gemm_mainloop(
    const __nv_bfloat16* __restrict__ Ahi, const __nv_bfloat16* __restrict__ Alo,
    const __nv_bfloat16* __restrict__ Bthi, const __nv_bfloat16* __restrict__ Btlo,
    int K, int m0, int n0, uint32_t sbase, float (&acc)[4][8][4])
{
    const int tid  = threadIdx.x;
    const int wid  = tid >> 5;
    const int lane = tid & 31;
    const int wm = (wid >> 1) * 64;
    const int wn = (wid & 1) * 64;

    auto load_stage = [&](int s, int kbase) {
        uint32_t st = sbase + (uint32_t)s * STG_B;
        #pragma unroll
        for (int it = 0; it < 4; it++) {
            int c   = tid + it * 128;
            int row = c >> 2;
            int ch  = c & 3;
            uint32_t so = st + swz((uint32_t)(row * 64 + ch * 16));
            size_t goa = (size_t)(m0 + row) * K + kbase + ch * 8;
            size_t gob = (size_t)(n0 + row) * K + kbase + ch * 8;
            cp16(so + 0 * ARR_B, Ahi  + goa);
            cp16(so + 1 * ARR_B, Alo  + goa);
            cp16(so + 2 * ARR_B, Bthi + gob);
            cp16(so + 3 * ARR_B, Btlo + gob);
        }
    };

    #pragma unroll
    for (int i = 0; i < 4; i++)
        #pragma unroll
        for (int j = 0; j < 8; j++)
            #pragma unroll
            for (int v = 0; v < 4; v++) acc[i][j][v] = 0.f;

    const int nk = K / BK;
    load_stage(0, 0);
    CP_COMMIT();
    load_stage(1, BK);
    CP_COMMIT();

    const int a_row = lane & 15;
    const int a_k8  = (lane >> 4) * 8;
    const int b_row = (lane & 7) + ((lane >> 4) << 3);
    const int b_k8  = ((lane >> 3) & 1) * 8;

    int s_cur = 0, s_nxt = 2;
    for (int kc = 0; kc < nk; kc++) {
        if (kc < nk - 1) { CP_WAIT(1); } else { CP_WAIT(0); }
        __syncthreads();
        if (kc + 2 < nk) {
            load_stage(s_nxt, (kc + 2) * BK);
            CP_COMMIT();
        }
        const uint32_t stg = sbase + (uint32_t)s_cur * STG_B;

        #pragma unroll
        for (int k16 = 0; k16 < BK; k16 += 16) {
            uint32_t ah[4][4], al[4][4];
            #pragma unroll
            for (int mt = 0; mt < 4; mt++) {
                uint32_t off = swz((uint32_t)((wm + mt * 16 + a_row) * 64)
                                   + (k16 + a_k8) * 2);
                ldsm_x4(ah[mt], stg + off);
                ldsm_x4(al[mt], stg + 1 * ARR_B + off);
            }
            #pragma unroll
            for (int p = 0; p < 4; p++) {
                uint32_t bh[4], bl[4];
                uint32_t off = swz((uint32_t)((wn + p * 16 + b_row) * 64)
                                   + (k16 + b_k8) * 2);
                ldsm_x4(bh, stg + 2 * ARR_B + off);
                ldsm_x4(bl, stg + 3 * ARR_B + off);
                #pragma unroll
                for (int mt = 0; mt < 4; mt++) {
                    mma_bf16(acc[mt][2 * p + 0], ah[mt], bh[0], bh[1]);
                    mma_bf16(acc[mt][2 * p + 1], ah[mt], bh[2], bh[3]);
                }
                #pragma unroll
                for (int mt = 0; mt < 4; mt++) {
                    mma_bf16(acc[mt][2 * p + 0], ah[mt], bl[0], bl[1]);
                    mma_bf16(acc[mt][2 * p + 1], ah[mt], bl[2], bl[3]);
                }
                #pragma unroll
                for (int mt = 0; mt < 4; mt++) {
                    mma_bf16(acc[mt][2 * p + 0], al[mt], bh[0], bh[1]);
                    mma_bf16(acc[mt][2 * p + 1], al[mt], bh[2], bh[3]);
                }
            }
        }
        s_cur = (s_cur + 1 == 3) ? 0 : s_cur + 1;
        s_nxt = (s_nxt + 1 == 3) ? 0 : s_nxt + 1;
    }
}

// ---------------------------------------------------------------------------
// Persistent fused GEMM1 + GEMM2: 296 CTAs loop over 4608 tiles.
// tiles [0,512)    : query proj (8192 x 1024, K=512)
// tiles [512,4608) : kv proj   (32768 x 2048, K=256)
// ---------------------------------------------------------------------------
__global__ __launch_bounds__(128, 2) void gemm12_kernel()
{
    extern __shared__ __nv_bfloat16 smem[];
    char* smc = reinterpret_cast<char*>(smem);
    const uint32_t sbase = smem_u32(smem);
    const int tid  = threadIdx.x;
    const int wid  = tid >> 5;
    const int lane = tid & 31;
    const int wm = (wid >> 1) * 64;
    const int wn = (wid & 1) * 64;
    const int er = lane >> 2;
    const int ec = (lane & 3) * 2;

    for (int t = blockIdx.x; t < 4608; t += PERSIST_CTAS) {
        const bool g1 = t < 512;
        const __nv_bfloat16* Ahi  = g1 ? g_qhi   : g_kvhi;
        const __nv_bfloat16* Alo  = g1 ? g_qlo   : g_kvlo;
        const __nv_bfloat16* Bthi = g1 ? g_wqthi : g_wkvthi;
        const __nv_bfloat16* Btlo = g1 ? g_wqtlo : g_wkvtlo;
        __nv_bfloat16* Chi = g1 ? g_qphi : g_kvphi;
        __nv_bfloat16* Clo = g1 ? g_qplo : g_kvplo;
        const int K = g1 ? QD : KVD;
        const int N = g1 ? HID : 2 * HID;
        const int nbx = g1 ? 8 : 16;
        const int lb  = g1 ? t : t - 512;
        const int m0 = (lb / nbx) * BM;
        const int n0 = (lb % nbx) * BN;

        __syncthreads();   // protect prior epilogue smem reads from new loads

        float acc[4][8][4];
        gemm_mainloop(Ahi, Alo, Bthi, Btlo, K, m0, n0, sbase, acc);

        __syncthreads();
        #pragma unroll
        for (int mt = 0; mt < 4; mt++) {
            #pragma unroll
            for (int nt = 0; nt < 8; nt++) {
                #pragma unroll
                for (int half = 0; half < 2; half++) {
                    int r = wm + mt * 16 + er + half * 8;
                    int c = wn + nt * 8 + ec;
                    float v0 = acc[mt][nt][2 * half + 0];
                    float v1 = acc[mt][nt][2 * half + 1];
                    uint32_t hp = pack_bf16(v0, v1);
                    __nv_bfloat162 hb = *reinterpret_cast<__nv_bfloat162*>(&hp);
                    uint32_t lp = pack_bf16(v0 - __bfloat162float(hb.x),
                                            v1 - __bfloat162float(hb.y));
                    *reinterpret_cast<uint32_t*>(smc + r * EPIT + c * 2) = hp;
                    *reinterpret_cast<uint32_t*>(smc + EARR + r * EPIT + c * 2) = lp;
                }
            }
        }
        __syncthreads();
        #pragma unroll
        for (int it = 0; it < 16; it++) {
            int idx = tid + it * 128;
            int r = idx >> 4, ch = idx & 15;
            uint4 v = *reinterpret_cast<const uint4*>(smc + r * EPIT + ch * 16);
            uint4 w = *reinterpret_cast<const uint4*>(smc + EARR + r * EPIT + ch * 16);
            size_t g = (size_t)(m0 + r) * N + n0 + ch * 8;
            *reinterpret_cast<uint4*>(Chi + g) = v;
            *reinterpret_cast<uint4*>(Clo + g) = w;
        }
    }
}

// ---------------------------------------------------------------------------
// GEMM3: out = attn @ Wo + bo (fp32, smem-staged epilogue). Single wave.
// ---------------------------------------------------------------------------
__global__ __launch_bounds__(128, 2) void gemm3_kernel(
    float* __restrict__ C, const float* __restrict__ bias)
{
    extern __shared__ __nv_bfloat16 smem[];
    char* smc = reinterpret_cast<char*>(smem);
    const uint32_t sbase = smem_u32(smem);
    const int tid  = threadIdx.x;
    const int wid  = tid >> 5;
    const int lane = tid & 31;
    const int m0 = blockIdx.y * BM;
    const int n0 = blockIdx.x * BN;
    const int N = QD;

    float acc[4][8][4];
    gemm_mainloop(g_athi, g_atlo, g_wothi, g_wotlo, HID, m0, n0, sbase, acc);

    const int wm = (wid >> 1) * 64;
    const int wn = (wid & 1) * 64;
    const int er = lane >> 2;
    const int ec = (lane & 3) * 2;
    __syncthreads();
    #pragma unroll
    for (int mt = 0; mt < 4; mt++) {
        #pragma unroll
        for (int nt = 0; nt < 8; nt++) {
            #pragma unroll
            for (int half = 0; half < 2; half++) {
                int r = wm + mt * 16 + er + half * 8;
                int c = wn + nt * 8 + ec;
                float2 v = make_float2(acc[mt][nt][2 * half + 0],
                                       acc[mt][nt][2 * half + 1]);
                *reinterpret_cast<float2*>(smc + r * EPIT32 + c * 4) = v;
            }
        }
    }
    __syncthreads();
    #pragma unroll
    for (int it = 0; it < 32; it++) {
        int idx = tid + it * 128;
        int r = idx >> 5, ch = idx & 31;
        float4 v = *reinterpret_cast<const float4*>(smc + r * EPIT32 + ch * 16);
        float4 bv = *reinterpret_cast<const float4*>(bias + n0 + ch * 4);
        v.x += bv.x; v.y += bv.y; v.z += bv.z; v.w += bv.w;
        *reinterpret_cast<float4*>(C + (size_t)(m0 + r) * N + n0 + ch * 4) = v;
    }
}

// ---------------------------------------------------------------------------
// Prep: blocks [0,12288) splits; [12288,13824) smem-tiled transpose-splits.
// ---------------------------------------------------------------------------
__global__ __launch_bounds__(256) void prep_kernel(
    const float* __restrict__ q,   const float* __restrict__ kv,
    const float* __restrict__ Wq,  const float* __restrict__ Wkv,
    const float* __restrict__ Wo)
{
    const int tid = threadIdx.x;
    if (blockIdx.x < 12288) {
        int i = blockIdx.x * 256 + tid;
        const float* src; __nv_bfloat16 *hi, *lo; int base;
        if (i < 1048576) { src = q;  hi = g_qhi;  lo = g_qlo;  base = i; }
        else             { src = kv; hi = g_kvhi; lo = g_kvlo; base = i - 1048576; }
        float4 v = reinterpret_cast<const float4*>(src)[base];
        __nv_bfloat162 hp0 = __floats2bfloat162_rn(v.x, v.y);
        __nv_bfloat162 hp1 = __floats2bfloat162_rn(v.z, v.w);
        __nv_bfloat162 lp0 = __floats2bfloat162_rn(v.x - __bfloat162float(hp0.x),
                                                   v.y - __bfloat162float(hp0.y));
        __nv_bfloat162 lp1 = __floats2bfloat162_rn(v.z - __bfloat162float(hp1.x),
                                                   v.w - __bfloat162float(hp1.y));
        reinterpret_cast<__nv_bfloat162*>(hi)[2 * base + 0] = hp0;
        reinterpret_cast<__nv_bfloat162*>(hi)[2 * base + 1] = hp1;
        reinterpret_cast<__nv_bfloat162*>(lo)[2 * base + 0] = lp0;
        reinterpret_cast<__nv_bfloat162*>(lo)[2 * base + 1] = lp1;
        return;
    }

    __shared__ __nv_bfloat16 sh_hi[32][36];
    __shared__ __nv_bfloat16 sh_lo[32][36];

    int bt = blockIdx.x - 12288;
    const float* W; __nv_bfloat16 *Whi, *Wlo; int K, N, tn_cnt;
    if (bt < 512)       { W = Wq;  Whi = g_wqthi;  Wlo = g_wqtlo;  K = 512;  N = 1024; tn_cnt = 32; }
    else if (bt < 1024) { W = Wkv; Whi = g_wkvthi; Wlo = g_wkvtlo; K = 256;  N = 2048; tn_cnt = 64; bt -= 512; }
    else                { W = Wo;  Whi = g_wothi;  Wlo = g_wotlo;  K = 1024; N = 512;  tn_cnt = 16; bt -= 1024; }
    const int k0 = (bt / tn_cnt) * 32;
    const int n0 = (bt % tn_cnt) * 32;

    {
        int r  = tid >> 3;
        int c4 = (tid & 7) << 2;
        float4 v = *reinterpret_cast<const float4*>(
            W + (size_t)(k0 + r) * N + n0 + c4);
        float vv[4] = { v.x, v.y, v.z, v.w };
        #pragma unroll
        for (int i = 0; i < 4; i++) {
            __nv_bfloat16 h = __float2bfloat16_rn(vv[i]);
            sh_hi[c4 + i][r] = h;
            sh_lo[c4 + i][r] = __float2bfloat16_rn(vv[i] - __bfloat162float(h));
        }
    }
    __syncthreads();
    {
        int nl = tid >> 3;
        int k4 = (tid & 7) << 2;
        uint32_t h0 = pack_bf16(__bfloat162float(sh_hi[nl][k4 + 0]),
                                __bfloat162float(sh_hi[nl][k4 + 1]));
        uint32_t h1 = pack_bf16(__bfloat162float(sh_hi[nl][k4 + 2]),
                                __bfloat162float(sh_hi[nl][k4 + 3]));
        uint32_t l0 = pack_bf16(__bfloat162float(sh_lo[nl][k4 + 0]),
                                __bfloat162float(sh_lo[nl][k4 + 1]));
        uint32_t l1 = pack_bf16(__bfloat162float(sh_lo[nl][k4 + 2]),
                                __bfloat162float(sh_lo[nl][k4 + 3]));
        *reinterpret_cast<uint2*>(Whi + (size_t)(n0 + nl) * K + k0 + k4) =
            make_uint2(h0, h1);
        *reinterpret_cast<uint2*>(Wlo + (size_t)(n0 + nl) * K + k0 + k4) =
            make_uint2(l0, l1);
    }
}

// ---------------------------------------------------------------------------
// Persistent HMMA flash attention: 296 CTAs loop over 1024 (b,h) tiles.
// 8 warps x 16 q-rows each, single barrier per jt, smem-staged epilogue.
// ---------------------------------------------------------------------------
#define AQ_HI 0u
#define AQ_LO 16384u
#define ASTG  32768u
#define AST_SZ 32768u
#define AK_HI 0u
#define AK_LO 8192u
#define AV_HI 16384u
#define AV_LO 24576u
#define ATT_SMEM (32768 + 2 * 32768)
#define AEPIT 144u
#define AEARR 18432u

__global__ __launch_bounds__(256, 2) void attn_mma_kernel()
{
    extern __shared__ char asmem[];
    const uint32_t sbase = smem_u32(asmem);
    const int tid  = threadIdx.x;
    const int wid  = tid >> 5;
    const int lane = tid & 31;
    const float scale = 0.125f;

    const int a_row = lane & 15;
    const int a_k8  = (lane >> 4) * 8;
    const int b_row = (lane & 7) + ((lane >> 4) << 3);
    const int b_k8  = ((lane >> 3) & 1) * 8;

    for (int bh = blockIdx.x; bh < B_ASSETS * NH; bh += PERSIST_CTAS) {
        const int b = bh >> 4;
        const int h = bh & 15;

        __syncthreads();   // protect prior tile's smem reads

        // ---- stage Q tile (128 x 64 hi/lo) ----
        for (int c = tid; c < 1024; c += 256) {
            int row = c >> 3, ch = c & 7;
            uint32_t so = swz((uint32_t)(row * 128 + ch * 16));
            size_t g = (size_t)(b * 128 + row) * 1024 + h * 64 + ch * 8;
            *reinterpret_cast<uint4*>(asmem + AQ_HI + so) =
                *reinterpret_cast<const uint4*>(g_qphi + g);
            *reinterpret_cast<uint4*>(asmem + AQ_LO + so) =
                *reinterpret_cast<const uint4*>(g_qplo + g);
        }

        auto load_kv = [&](int jt, int s) {
            uint32_t st = sbase + ASTG + (uint32_t)s * AST_SZ;
            #pragma unroll
            for (int half = 0; half < 2; half++) {
                int c = tid + half * 256;
                int row = c >> 3, ch = c & 7;
                uint32_t so = swz((uint32_t)(row * 128 + ch * 16));
                size_t kr = (size_t)(b * J_WIN + jt * 64 + row) * 2048 + h * 64 + ch * 8;
                cp16(st + AK_HI + so, g_kvphi + kr);
                cp16(st + AK_LO + so, g_kvplo + kr);
                cp16(st + AV_HI + so, g_kvphi + kr + 1024);
                cp16(st + AV_LO + so, g_kvplo + kr + 1024);
            }
        };

        load_kv(0, 0);
        CP_COMMIT();

        __syncthreads();
        uint32_t qah[4][4], qal[4][4];
        #pragma unroll
        for (int kc = 0; kc < 4; kc++) {
            uint32_t off = swz((uint32_t)((wid * 16 + a_row) * 128)
                               + (kc * 16 + a_k8) * 2);
            ldsm_x4(qah[kc], sbase + AQ_HI + off);
            ldsm_x4(qal[kc], sbase + AQ_LO + off);
        }

        float oacc[8][4];
        #pragma unroll
        for (int d = 0; d < 8; d++)
            #pragma unroll
            for (int v = 0; v < 4; v++) oacc[d][v] = 0.f;
        float m0 = -INFINITY, m1 = -INFINITY, l0 = 0.f, l1 = 0.f;

        for (int jt = 0; jt < 8; jt++) {
            CP_WAIT(0);
            __syncthreads();
            if (jt + 1 < 8) {
                load_kv(jt + 1, (jt + 1) & 1);
                CP_COMMIT();
            }
            const uint32_t st = sbase + ASTG + (uint32_t)(jt & 1) * AST_SZ;

            float sacc[8][4];
            #pragma unroll
            for (int p = 0; p < 8; p++)
                #pragma unroll
                for (int v = 0; v < 4; v++) sacc[p][v] = 0.f;

            #pragma unroll
            for (int kc = 0; kc < 4; kc++) {
                #pragma unroll
                for (int p = 0; p < 4; p++) {
                    uint32_t bh4[4], bl4[4];
                    uint32_t off = swz((uint32_t)((p * 16 + b_row) * 128)
                                       + (kc * 16 + b_k8) * 2);
                    ldsm_x4(bh4, st + AK_HI + off);
                    ldsm_x4(bl4, st + AK_LO + off);
                    mma_bf16(sacc[2 * p + 0], qah[kc], bh4[0], bh4[1]);
                    mma_bf16(sacc[2 * p + 1], qah[kc], bh4[2], bh4[3]);
                    mma_bf16(sacc[2 * p + 0], qah[kc], bl4[0], bl4[1]);
                    mma_bf16(sacc[2 * p + 1], qah[kc], bl4[2], bl4[3]);
                    mma_bf16(sacc[2 * p + 0], qal[kc], bh4[0], bh4[1]);
                    mma_bf16(sacc[2 * p + 1], qal[kc], bh4[2], bh4[3]);
                }
            }

            float mx0 = -INFINITY, mx1 = -INFINITY;
            #pragma unroll
            for (int nt = 0; nt < 8; nt++) {
                mx0 = fmaxf(mx0, fmaxf(sacc[nt][0], sacc[nt][1]));
                mx1 = fmaxf(mx1, fmaxf(sacc[nt][2], sacc[nt][3]));
            }
            #pragma unroll
            for (int o = 1; o <= 2; o <<= 1) {
                mx0 = fmaxf(mx0, __shfl_xor_sync(0xffffffffu, mx0, o));
                mx1 = fmaxf(mx1, __shfl_xor_sync(0xffffffffu, mx1, o));
            }
            float m0n = fmaxf(m0, mx0 * scale);
            float m1n = fmaxf(m1, mx1 * scale);
            float f0 = __expf(m0 - m0n);
            float f1 = __expf(m1 - m1n);
            m0 = m0n; m1 = m1n;

            float s0 = 0.f, s1 = 0.f;
            #pragma unroll
            for (int nt = 0; nt < 8; nt++) {
                float p0 = __expf(sacc[nt][0] * scale - m0n);
                float p1 = __expf(sacc[nt][1] * scale - m0n);
                float p2 = __expf(sacc[nt][2] * scale - m1n);
                float p3 = __expf(sacc[nt][3] * scale - m1n);
                sacc[nt][0] = p0; sacc[nt][1] = p1;
                sacc[nt][2] = p2; sacc[nt][3] = p3;
                s0 += p0 + p1; s1 += p2 + p3;
            }
            #pragma unroll
            for (int o = 1; o <= 2; o <<= 1) {
                s0 += __shfl_xor_sync(0xffffffffu, s0, o);
                s1 += __shfl_xor_sync(0xffffffffu, s1, o);
            }
            l0 = l0 * f0 + s0;
            l1 = l1 * f1 + s1;
            #pragma unroll
            for (int d = 0; d < 8; d++) {
                oacc[d][0] *= f0; oacc[d][1] *= f0;
                oacc[d][2] *= f1; oacc[d][3] *= f1;
            }

            #pragma unroll
            for (int kcp = 0; kcp < 4; kcp++) {
                uint32_t pa_h[4], pa_l[4];
                #pragma unroll
                for (int tpair = 0; tpair < 2; tpair++) {
                    int nt = 2 * kcp + tpair;
                    float v0 = sacc[nt][0], v1 = sacc[nt][1];
                    float v2 = sacc[nt][2], v3 = sacc[nt][3];
                    uint32_t hp0 = pack_bf16(v0, v1);
                    uint32_t hp1 = pack_bf16(v2, v3);
                    __nv_bfloat162 hb0 = *reinterpret_cast<__nv_bfloat162*>(&hp0);
                    __nv_bfloat162 hb1 = *reinterpret_cast<__nv_bfloat162*>(&hp1);
                    pa_h[2 * tpair + 0] = hp0;
                    pa_h[2 * tpair + 1] = hp1;
                    pa_l[2 * tpair + 0] = pack_bf16(v0 - __bfloat162float(hb0.x),
                                                    v1 - __bfloat162float(hb0.y));
                    pa_l[2 * tpair + 1] = pack_bf16(v2 - __bfloat162float(hb1.x),
                                                    v3 - __bfloat162float(hb1.y));
                }
                #pragma unroll
                for (int dp = 0; dp < 4; dp++) {
                    uint32_t vh[4], vl[4];
                    uint32_t off = swz((uint32_t)((kcp * 16 + (lane & 15)) * 128)
                                       + (dp * 16 + (lane >> 4) * 8) * 2);
                    ldsm_x4t(vh, st + AV_HI + off);
                    ldsm_x4t(vl, st + AV_LO + off);
                    mma_bf16(oacc[2 * dp + 0], pa_h, vh[0], vh[1]);
                    mma_bf16(oacc[2 * dp + 1], pa_h, vh[2], vh[3]);
                    mma_bf16(oacc[2 * dp + 0], pa_l, vh[0], vh[1]);
                    mma_bf16(oacc[2 * dp + 1], pa_l, vh[2], vh[3]);
                    mma_bf16(oacc[2 * dp + 0], pa_h, vl[0], vl[1]);
                    mma_bf16(oacc[2 * dp + 1], pa_h, vl[2], vl[3]);
                }
            }
        }

        const float inv0 = 1.f / l0;
        const float inv1 = 1.f / l1;
        __syncthreads();
        #pragma unroll
        for (int dt = 0; dt < 8; dt++) {
            #pragma unroll
            for (int half = 0; half < 2; half++) {
                int r = wid * 16 + (lane >> 2) + half * 8;
                int c = (lane & 3) * 2 + dt * 8;
                float inv = half ? inv1 : inv0;
                float v0 = oacc[dt][2 * half + 0] * inv;
                float v1 = oacc[dt][2 * half + 1] * inv;
                uint32_t hp = pack_bf16(v0, v1);
                __nv_bfloat162 hb = *reinterpret_cast<__nv_bfloat162*>(&hp);
                uint32_t lp = pack_bf16(v0 - __bfloat162float(hb.x),
                                        v1 - __bfloat162float(hb.y));
                *reinterpret_cast<uint32_t*>(asmem + r * AEPIT + c * 2) = hp;
                *reinterpret_cast<uint32_t*>(asmem + AEARR + r * AEPIT + c * 2) = lp;
            }
        }
        __syncthreads();
        #pragma unroll
        for (int it = 0; it < 4; it++) {
            int idx = tid + it * 256;
            int r = idx >> 3, ch = idx & 7;
            uint4 v = *reinterpret_cast<const uint4*>(asmem + r * AEPIT + ch * 16);
            uint4 w = *reinterpret_cast<const uint4*>(asmem + AEARR + r * AEPIT + ch * 16);
            size_t g = (size_t)(b * 128 + r) * 1024 + h * 64 + ch * 8;
            *reinterpret_cast<uint4*>(g_athi + g) = v;
            *reinterpret_cast<uint4*>(g_atlo + g) = w;
        }
    }
}

// ---------------------------------------------------------------------------
// Launch
// ---------------------------------------------------------------------------
extern "C" void kernel_launch(void* const* d_in, const int* in_sizes, int n_in,
                              void* d_out, int out_size)
{
    const float* q   = (const float*)d_in[0];
    const float* kv  = (const float*)d_in[1];
    const float* Wq  = (const float*)d_in[2];
    const float* Wkv = (const float*)d_in[3];
    const float* Wo  = (const float*)d_in[4];
    const float* bo  = (const float*)d_in[5];
    float* out = (float*)d_out;

    cudaFuncSetAttribute(gemm12_kernel,
                         cudaFuncAttributeMaxDynamicSharedMemorySize, GEMM_SMEM);
    cudaFuncSetAttribute(gemm3_kernel,
                         cudaFuncAttributeMaxDynamicSharedMemorySize, GEMM_SMEM);
    cudaFuncSetAttribute(attn_mma_kernel,
                         cudaFuncAttributeMaxDynamicSharedMemorySize, ATT_SMEM);

    // 1) prep: splits + tiled transpose-splits
    prep_kernel<<<13824, 256>>>(q, kv, Wq, Wkv, Wo);

    // 2) persistent fused query+kv projections -> bf16 hi/lo
    gemm12_kernel<<<PERSIST_CTAS, 128, GEMM_SMEM>>>();

    // 3) persistent flash attention (HMMA) -> bf16 hi/lo
    attn_mma_kernel<<<PERSIST_CTAS, 256, ATT_SMEM>>>();

    // 4) out = attn @ Wo + bo (fp32, staged epilogue)
    gemm3_kernel<<<dim3(QD / BN, 8192 / BM), 128, GEMM_SMEM>>>(out, bo);
}

// round 11
// speedup vs baseline: 1.0725x; 1.0725x over previous
#include <cuda_runtime.h>
#include <cuda_bf16.h>
#include <cstdint>
#include <math.h>

// ---------------------------------------------------------------------------
//   q (64,128,512)  kv (64,512,256)  Wq (512,1024)  Wkv (256,2048)
//   Wo (1024,512)  bo (512)  out (64,128,512)
// HMMA everywhere, fp32 via bf16 hi/lo 3-split. R9 scheduling (non-persistent,
// HW-overlapped waves). Softmax scale folded into GEMM1 epilogue (exact 2^-3).
// ---------------------------------------------------------------------------

#define B_ASSETS 64
#define I_LAT    128
#define J_WIN    512
#define QD       512
#define KVD      256
#define HID      1024
#define NH       16
#define HD       64

// ------------------------- scratch (no cudaMalloc) -------------------------
__device__ __nv_bfloat16  g_qhi  [8192u  * 512u],  g_qlo  [8192u  * 512u];
__device__ __nv_bfloat16  g_kvhi [32768u * 256u],  g_kvlo [32768u * 256u];
__device__ __nv_bfloat16  g_qphi [8192u  * 1024u], g_qplo [8192u  * 1024u];
__device__ __nv_bfloat16  g_kvphi[32768u * 2048u], g_kvplo[32768u * 2048u];
__device__ __nv_bfloat16  g_athi [8192u  * 1024u], g_atlo [8192u  * 1024u];
__device__ __nv_bfloat16  g_wqthi [1024u * 512u],  g_wqtlo [1024u * 512u];
__device__ __nv_bfloat16  g_wkvthi[2048u * 256u],  g_wkvtlo[2048u * 256u];
__device__ __nv_bfloat16  g_wothi [512u * 1024u],  g_wotlo [512u * 1024u];

// ------------------------------ PTX helpers --------------------------------
__device__ __forceinline__ uint32_t smem_u32(const void* p) {
    uint32_t a;
    asm("{ .reg .u64 t; cvta.to.shared.u64 t, %1; cvt.u32.u64 %0, t; }"
        : "=r"(a) : "l"(p));
    return a;
}
__device__ __forceinline__ void cp16(uint32_t dst, const void* src) {
    asm volatile("cp.async.cg.shared.global [%0], [%1], 16;"
                 :: "r"(dst), "l"(src));
}
#define CP_COMMIT() asm volatile("cp.async.commit_group;" ::: "memory")
#define CP_WAIT(n)  asm volatile("cp.async.wait_group %0;" :: "n"(n) : "memory")

__device__ __forceinline__ void ldsm_x4(uint32_t (&r)[4], uint32_t addr) {
    asm volatile("ldmatrix.sync.aligned.m8n8.x4.shared.b16 {%0,%1,%2,%3}, [%4];"
                 : "=r"(r[0]), "=r"(r[1]), "=r"(r[2]), "=r"(r[3]) : "r"(addr));
}
__device__ __forceinline__ void ldsm_x4t(uint32_t (&r)[4], uint32_t addr) {
    asm volatile("ldmatrix.sync.aligned.m8n8.x4.trans.shared.b16 {%0,%1,%2,%3}, [%4];"
                 : "=r"(r[0]), "=r"(r[1]), "=r"(r[2]), "=r"(r[3]) : "r"(addr));
}
__device__ __forceinline__ void mma_bf16(float (&d)[4],
                                         const uint32_t (&a)[4],
                                         uint32_t b0, uint32_t b1) {
    asm volatile(
        "mma.sync.aligned.m16n8k16.row.col.f32.bf16.bf16.f32 "
        "{%0,%1,%2,%3}, {%4,%5,%6,%7}, {%8,%9}, {%0,%1,%2,%3};"
        : "+f"(d[0]), "+f"(d[1]), "+f"(d[2]), "+f"(d[3])
        : "r"(a[0]), "r"(a[1]), "r"(a[2]), "r"(a[3]), "r"(b0), "r"(b1));
}
__device__ __forceinline__ uint32_t pack_bf16(float lo, float hi) {
    __nv_bfloat162 h = __floats2bfloat162_rn(lo, hi);
    return *reinterpret_cast<uint32_t*>(&h);
}
__device__ __forceinline__ uint32_t swz(uint32_t b) {
    return b ^ ((b >> 3) & 0x70);
}

// ---------------------------------------------------------------------------
// GEMM machinery: CTA 128x128 (128 threads, 4 warps, 2x2 of 64x64 tiles),
// BK=32, 3-stage cp.async, swizzled smem.
// ---------------------------------------------------------------------------
#define BM 128
#define BN 128
#define BK 32
#define ARR_B 8192u
#define STG_B 32768u
#define GEMM_SMEM (3 * 32768)
#define EPIT   272u
#define EARR   34816u
#define EPIT32 528u

__device__ __forceinline__ void gemm_mainloop(
    const __nv_bfloat16* __restrict__ Ahi, const __nv_bfloat16* __restrict__ Alo,
    const __nv_bfloat16* __restrict__ Bthi, const __nv_bfloat16* __restrict__ Btlo,
    int K, int m0, int n0, uint32_t sbase, float (&acc)[4][8][4])
{
    const int tid  = threadIdx.x;
    const int wid  = tid >> 5;
    const int lane = tid & 31;
    const int wm = (wid >> 1) * 64;
    const int wn = (wid & 1) * 64;

    auto load_stage = [&](int s, int kbase) {
        uint32_t st = sbase + (uint32_t)s * STG_B;
        #pragma unroll
        for (int it = 0; it < 4; it++) {
            int c   = tid + it * 128;
            int row = c >> 2;
            int ch  = c & 3;
            uint32_t so = st + swz((uint32_t)(row * 64 + ch * 16));
            size_t goa = (size_t)(m0 + row) * K + kbase + ch * 8;
            size_t gob = (size_t)(n0 + row) * K + kbase + ch * 8;
            cp16(so + 0 * ARR_B, Ahi  + goa);
            cp16(so + 1 * ARR_B, Alo  + goa);
            cp16(so + 2 * ARR_B, Bthi + gob);
            cp16(so + 3 * ARR_B, Btlo + gob);
        }
    };

    #pragma unroll
    for (int i = 0; i < 4; i++)
        #pragma unroll
        for (int j = 0; j < 8; j++)
            #pragma unroll
            for (int v = 0; v < 4; v++) acc[i][j][v] = 0.f;

    const int nk = K / BK;
    load_stage(0, 0);
    CP_COMMIT();
    load_stage(1, BK);
    CP_COMMIT();

    const int a_row = lane & 15;
    const int a_k8  = (lane >> 4) * 8;
    const int b_row = (lane & 7) + ((lane >> 4) << 3);
    const int b_k8  = ((lane >> 3) & 1) * 8;

    int s_cur = 0, s_nxt = 2;
    for (int kc = 0; kc < nk; kc++) {
        if (kc < nk - 1) { CP_WAIT(1); } else { CP_WAIT(0); }
        __syncthreads();
        if (kc + 2 < nk) {
            load_stage(s_nxt, (kc + 2) * BK);
            CP_COMMIT();
        }
        const uint32_t stg = sbase + (uint32_t)s_cur * STG_B;

        #pragma unroll
        for (int k16 = 0; k16 < BK; k16 += 16) {
            uint32_t ah[4][4], al[4][4];
            #pragma unroll
            for (int mt = 0; mt < 4; mt++) {
                uint32_t off = swz((uint32_t)((wm + mt * 16 + a_row) * 64)
                                   + (k16 + a_k8) * 2);
                ldsm_x4(ah[mt], stg + off);
                ldsm_x4(al[mt], stg + 1 * ARR_B + off);
            }
            #pragma unroll
            for (int p = 0; p < 4; p++) {
                uint32_t bh[4], bl[4];
                uint32_t off = swz((uint32_t)((wn + p * 16 + b_row) * 64)
                                   + (k16 + b_k8) * 2);
                ldsm_x4(bh, stg + 2 * ARR_B + off);
                ldsm_x4(bl, stg + 3 * ARR_B + off);
                #pragma unroll
                for (int mt = 0; mt < 4; mt++) {
                    mma_bf16(acc[mt][2 * p + 0], ah[mt], bh[0], bh[1]);
                    mma_bf16(acc[mt][2 * p + 1], ah[mt], bh[2], bh[3]);
                }
                #pragma unroll
                for (int mt = 0; mt < 4; mt++) {
                    mma_bf16(acc[mt][2 * p + 0], ah[mt], bl[0], bl[1]);
                    mma_bf16(acc[mt][2 * p + 1], ah[mt], bl[2], bl[3]);
                }
                #pragma unroll
                for (int mt = 0; mt < 4; mt++) {
                    mma_bf16(acc[mt][2 * p + 0], al[mt], bh[0], bh[1]);
                    mma_bf16(acc[mt][2 * p + 1], al[mt], bh[2], bh[3]);
                }
            }
        }
        s_cur = (s_cur + 1 == 3) ? 0 : s_cur + 1;
        s_nxt = (s_nxt + 1 == 3) ? 0 : s_nxt + 1;
    }
}

// ---------------------------------------------------------------------------
// Fused GEMM1 + GEMM2: blocks [0,512) query proj (output pre-scaled by 1/8),
// blocks [512,4608) kv proj.
// ---------------------------------------------------------------------------
__global__ __launch_bounds__(128, 2) void gemm12_kernel()
{
    extern __shared__ __nv_bfloat16 smem[];
    char* smc = reinterpret_cast<char*>(smem);
    const uint32_t sbase = smem_u32(smem);
    const int tid  = threadIdx.x;
    const int wid  = tid >> 5;
    const int lane = tid & 31;

    const int bid = blockIdx.x;
    const bool g1 = bid < 512;
    const __nv_bfloat16* Ahi  = g1 ? g_qhi   : g_kvhi;
    const __nv_bfloat16* Alo  = g1 ? g_qlo   : g_kvlo;
    const __nv_bfloat16* Bthi = g1 ? g_wqthi : g_wkvthi;
    const __nv_bfloat16* Btlo = g1 ? g_wqtlo : g_wkvtlo;
    __nv_bfloat16* Chi = g1 ? g_qphi : g_kvphi;
    __nv_bfloat16* Clo = g1 ? g_qplo : g_kvplo;
    const int K = g1 ? QD : KVD;
    const int N = g1 ? HID : 2 * HID;
    const int nbx = g1 ? 8 : 16;
    const int lb  = g1 ? bid : bid - 512;
    const int m0 = (lb / nbx) * BM;
    const int n0 = (lb % nbx) * BN;
    const float oscale = g1 ? 0.125f : 1.0f;   // fold softmax scale into Q

    float acc[4][8][4];
    gemm_mainloop(Ahi, Alo, Bthi, Btlo, K, m0, n0, sbase, acc);

    const int wm = (wid >> 1) * 64;
    const int wn = (wid & 1) * 64;
    const int er = lane >> 2;
    const int ec = (lane & 3) * 2;
    __syncthreads();
    #pragma unroll
    for (int mt = 0; mt < 4; mt++) {
        #pragma unroll
        for (int nt = 0; nt < 8; nt++) {
            #pragma unroll
            for (int half = 0; half < 2; half++) {
                int r = wm + mt * 16 + er + half * 8;
                int c = wn + nt * 8 + ec;
                float v0 = acc[mt][nt][2 * half + 0] * oscale;
                float v1 = acc[mt][nt][2 * half + 1] * oscale;
                uint32_t hp = pack_bf16(v0, v1);
                __nv_bfloat162 hb = *reinterpret_cast<__nv_bfloat162*>(&hp);
                uint32_t lp = pack_bf16(v0 - __bfloat162float(hb.x),
                                        v1 - __bfloat162float(hb.y));
                *reinterpret_cast<uint32_t*>(smc + r * EPIT + c * 2) = hp;
                *reinterpret_cast<uint32_t*>(smc + EARR + r * EPIT + c * 2) = lp;
            }
        }
    }
    __syncthreads();
    #pragma unroll
    for (int it = 0; it < 16; it++) {
        int idx = tid + it * 128;
        int r = idx >> 4, ch = idx & 15;
        uint4 v = *reinterpret_cast<const uint4*>(smc + r * EPIT + ch * 16);
        uint4 w = *reinterpret_cast<const uint4*>(smc + EARR + r * EPIT + ch * 16);
        size_t g = (size_t)(m0 + r) * N + n0 + ch * 8;
        *reinterpret_cast<uint4*>(Chi + g) = v;
        *reinterpret_cast<uint4*>(Clo + g) = w;
    }
}

// ---------------------------------------------------------------------------
// GEMM3: out = attn @ Wo + bo (fp32, smem-staged epilogue)
// ---------------------------------------------------------------------------
__global__ __launch_bounds__(128, 2) void gemm3_kernel(
    float* __restrict__ C, const float* __restrict__ bias)
{
    extern __shared__ __nv_bfloat16 smem[];
    char* smc = reinterpret_cast<char*>(smem);
    const uint32_t sbase = smem_u32(smem);
    const int tid  = threadIdx.x;
    const int wid  = tid >> 5;
    const int lane = tid & 31;
    const int m0 = blockIdx.y * BM;
    const int n0 = blockIdx.x * BN;
    const int N = QD;

    float acc[4][8][4];
    gemm_mainloop(g_athi, g_atlo, g_wothi, g_wotlo, HID, m0, n0, sbase, acc);

    const int wm = (wid >> 1) * 64;
    const int wn = (wid & 1) * 64;
    const int er = lane >> 2;
    const int ec = (lane & 3) * 2;
    __syncthreads();
    #pragma unroll
    for (int mt = 0; mt < 4; mt++) {
        #pragma unroll
        for (int nt = 0; nt < 8; nt++) {
            #pragma unroll
            for (int half = 0; half < 2; half++) {
                int r = wm + mt * 16 + er + half * 8;
                int c = wn + nt * 8 + ec;
                float2 v = make_float2(acc[mt][nt][2 * half + 0],
                                       acc[mt][nt][2 * half + 1]);
                *reinterpret_cast<float2*>(smc + r * EPIT32 + c * 4) = v;
            }
        }
    }
    __syncthreads();
    #pragma unroll
    for (int it = 0; it < 32; it++) {
        int idx = tid + it * 128;
        int r = idx >> 5, ch = idx & 31;
        float4 v = *reinterpret_cast<const float4*>(smc + r * EPIT32 + ch * 16);
        float4 bv = *reinterpret_cast<const float4*>(bias + n0 + ch * 4);
        v.x += bv.x; v.y += bv.y; v.z += bv.z; v.w += bv.w;
        *reinterpret_cast<float4*>(C + (size_t)(m0 + r) * N + n0 + ch * 4) = v;
    }
}

// ---------------------------------------------------------------------------
// Prep: blocks [0,12288) splits; [12288,13824) smem-tiled transpose-splits.
// ---------------------------------------------------------------------------
__global__ __launch_bounds__(256) void prep_kernel(
    const float* __restrict__ q,   const float* __restrict__ kv,
    const float* __restrict__ Wq,  const float* __restrict__ Wkv,
    const float* __restrict__ Wo)
{
    const int tid = threadIdx.x;
    if (blockIdx.x < 12288) {
        int i = blockIdx.x * 256 + tid;
        const float* src; __nv_bfloat16 *hi, *lo; int base;
        if (i < 1048576) { src = q;  hi = g_qhi;  lo = g_qlo;  base = i; }
        else             { src = kv; hi = g_kvhi; lo = g_kvlo; base = i - 1048576; }
        float4 v = reinterpret_cast<const float4*>(src)[base];
        __nv_bfloat162 hp0 = __floats2bfloat162_rn(v.x, v.y);
        __nv_bfloat162 hp1 = __floats2bfloat162_rn(v.z, v.w);
        __nv_bfloat162 lp0 = __floats2bfloat162_rn(v.x - __bfloat162float(hp0.x),
                                                   v.y - __bfloat162float(hp0.y));
        __nv_bfloat162 lp1 = __floats2bfloat162_rn(v.z - __bfloat162float(hp1.x),
                                                   v.w - __bfloat162float(hp1.y));
        reinterpret_cast<__nv_bfloat162*>(hi)[2 * base + 0] = hp0;
        reinterpret_cast<__nv_bfloat162*>(hi)[2 * base + 1] = hp1;
        reinterpret_cast<__nv_bfloat162*>(lo)[2 * base + 0] = lp0;
        reinterpret_cast<__nv_bfloat162*>(lo)[2 * base + 1] = lp1;
        return;
    }

    __shared__ __nv_bfloat16 sh_hi[32][36];
    __shared__ __nv_bfloat16 sh_lo[32][36];

    int bt = blockIdx.x - 12288;
    const float* W; __nv_bfloat16 *Whi, *Wlo; int K, N, tn_cnt;
    if (bt < 512)       { W = Wq;  Whi = g_wqthi;  Wlo = g_wqtlo;  K = 512;  N = 1024; tn_cnt = 32; }
    else if (bt < 1024) { W = Wkv; Whi = g_wkvthi; Wlo = g_wkvtlo; K = 256;  N = 2048; tn_cnt = 64; bt -= 512; }
    else                { W = Wo;  Whi = g_wothi;  Wlo = g_wotlo;  K = 1024; N = 512;  tn_cnt = 16; bt -= 1024; }
    const int k0 = (bt / tn_cnt) * 32;
    const int n0 = (bt % tn_cnt) * 32;

    {
        int r  = tid >> 3;
        int c4 = (tid & 7) << 2;
        float4 v = *reinterpret_cast<const float4*>(
            W + (size_t)(k0 + r) * N + n0 + c4);
        float vv[4] = { v.x, v.y, v.z, v.w };
        #pragma unroll
        for (int i = 0; i < 4; i++) {
            __nv_bfloat16 h = __float2bfloat16_rn(vv[i]);
            sh_hi[c4 + i][r] = h;
            sh_lo[c4 + i][r] = __float2bfloat16_rn(vv[i] - __bfloat162float(h));
        }
    }
    __syncthreads();
    {
        int nl = tid >> 3;
        int k4 = (tid & 7) << 2;
        uint32_t h0 = pack_bf16(__bfloat162float(sh_hi[nl][k4 + 0]),
                                __bfloat162float(sh_hi[nl][k4 + 1]));
        uint32_t h1 = pack_bf16(__bfloat162float(sh_hi[nl][k4 + 2]),
                                __bfloat162float(sh_hi[nl][k4 + 3]));
        uint32_t l0 = pack_bf16(__bfloat162float(sh_lo[nl][k4 + 0]),
                                __bfloat162float(sh_lo[nl][k4 + 1]));
        uint32_t l1 = pack_bf16(__bfloat162float(sh_lo[nl][k4 + 2]),
                                __bfloat162float(sh_lo[nl][k4 + 3]));
        *reinterpret_cast<uint2*>(Whi + (size_t)(n0 + nl) * K + k0 + k4) =
            make_uint2(h0, h1);
        *reinterpret_cast<uint2*>(Wlo + (size_t)(n0 + nl) * K + k0 + k4) =
            make_uint2(l0, l1);
    }
}

// ---------------------------------------------------------------------------
// HMMA flash attention: CTA = (b, h), 8 warps x 16 rows; single barrier per
// jt; Q arrives pre-scaled by 1/8 so softmax uses raw S values.
// ---------------------------------------------------------------------------
#define AQ_HI 0u
#define AQ_LO 16384u
#define ASTG  32768u
#define AST_SZ 32768u
#define AK_HI 0u
#define AK_LO 8192u
#define AV_HI 16384u
#define AV_LO 24576u
#define ATT_SMEM (32768 + 2 * 32768)
#define AEPIT 144u
#define AEARR 18432u

__global__ __launch_bounds__(256, 2) void attn_mma_kernel()
{
    extern __shared__ char asmem[];
    const uint32_t sbase = smem_u32(asmem);
    const int b = blockIdx.x >> 4;
    const int h = blockIdx.x & 15;
    const int tid  = threadIdx.x;
    const int wid  = tid >> 5;
    const int lane = tid & 31;

    for (int c = tid; c < 1024; c += 256) {
        int row = c >> 3, ch = c & 7;
        uint32_t so = swz((uint32_t)(row * 128 + ch * 16));
        size_t g = (size_t)(b * 128 + row) * 1024 + h * 64 + ch * 8;
        *reinterpret_cast<uint4*>(asmem + AQ_HI + so) =
            *reinterpret_cast<const uint4*>(g_qphi + g);
        *reinterpret_cast<uint4*>(asmem + AQ_LO + so) =
            *reinterpret_cast<const uint4*>(g_qplo + g);
    }

    auto load_kv = [&](int jt, int s) {
        uint32_t st = sbase + ASTG + (uint32_t)s * AST_SZ;
        #pragma unroll
        for (int half = 0; half < 2; half++) {
            int c = tid + half * 256;
            int row = c >> 3, ch = c & 7;
            uint32_t so = swz((uint32_t)(row * 128 + ch * 16));
            size_t kr = (size_t)(b * J_WIN + jt * 64 + row) * 2048 + h * 64 + ch * 8;
            cp16(st + AK_HI + so, g_kvphi + kr);
            cp16(st + AK_LO + so, g_kvplo + kr);
            cp16(st + AV_HI + so, g_kvphi + kr + 1024);
            cp16(st + AV_LO + so, g_kvplo + kr + 1024);
        }
    };

    load_kv(0, 0);
    CP_COMMIT();

    const int a_row = lane & 15;
    const int a_k8  = (lane >> 4) * 8;
    const int b_row = (lane & 7) + ((lane >> 4) << 3);
    const int b_k8  = ((lane >> 3) & 1) * 8;

    __syncthreads();
    uint32_t qah[4][4], qal[4][4];
    #pragma unroll
    for (int kc = 0; kc < 4; kc++) {
        uint32_t off = swz((uint32_t)((wid * 16 + a_row) * 128)
                           + (kc * 16 + a_k8) * 2);
        ldsm_x4(qah[kc], sbase + AQ_HI + off);
        ldsm_x4(qal[kc], sbase + AQ_LO + off);
    }

    float oacc[8][4];
    #pragma unroll
    for (int d = 0; d < 8; d++)
        #pragma unroll
        for (int v = 0; v < 4; v++) oacc[d][v] = 0.f;
    float m0 = -INFINITY, m1 = -INFINITY, l0 = 0.f, l1 = 0.f;

    for (int jt = 0; jt < 8; jt++) {
        CP_WAIT(0);
        __syncthreads();
        if (jt + 1 < 8) {
            load_kv(jt + 1, (jt + 1) & 1);
            CP_COMMIT();
        }
        const uint32_t st = sbase + ASTG + (uint32_t)(jt & 1) * AST_SZ;

        float sacc[8][4];
        #pragma unroll
        for (int p = 0; p < 8; p++)
            #pragma unroll
            for (int v = 0; v < 4; v++) sacc[p][v] = 0.f;

        #pragma unroll
        for (int kc = 0; kc < 4; kc++) {
            #pragma unroll
            for (int p = 0; p < 4; p++) {
                uint32_t bh[4], bl[4];
                uint32_t off = swz((uint32_t)((p * 16 + b_row) * 128)
                                   + (kc * 16 + b_k8) * 2);
                ldsm_x4(bh, st + AK_HI + off);
                ldsm_x4(bl, st + AK_LO + off);
                mma_bf16(sacc[2 * p + 0], qah[kc], bh[0], bh[1]);
                mma_bf16(sacc[2 * p + 1], qah[kc], bh[2], bh[3]);
                mma_bf16(sacc[2 * p + 0], qah[kc], bl[0], bl[1]);
                mma_bf16(sacc[2 * p + 1], qah[kc], bl[2], bl[3]);
                mma_bf16(sacc[2 * p + 0], qal[kc], bh[0], bh[1]);
                mma_bf16(sacc[2 * p + 1], qal[kc], bh[2], bh[3]);
            }
        }

        // ---- online softmax (S already includes the 1/8 scale via Q) ----
        float mx0 = -INFINITY, mx1 = -INFINITY;
        #pragma unroll
        for (int nt = 0; nt < 8; nt++) {
            mx0 = fmaxf(mx0, fmaxf(sacc[nt][0], sacc[nt][1]));
            mx1 = fmaxf(mx1, fmaxf(sacc[nt][2], sacc[nt][3]));
        }
        #pragma unroll
        for (int o = 1; o <= 2; o <<= 1) {
            mx0 = fmaxf(mx0, __shfl_xor_sync(0xffffffffu, mx0, o));
            mx1 = fmaxf(mx1, __shfl_xor_sync(0xffffffffu, mx1, o));
        }
        float m0n = fmaxf(m0, mx0);
        float m1n = fmaxf(m1, mx1);
        float f0 = __expf(m0 - m0n);
        float f1 = __expf(m1 - m1n);
        m0 = m0n; m1 = m1n;

        float s0 = 0.f, s1 = 0.f;
        #pragma unroll
        for (int nt = 0; nt < 8; nt++) {
            float p0 = __expf(sacc[nt][0] - m0n);
            float p1 = __expf(sacc[nt][1] - m0n);
            float p2 = __expf(sacc[nt][2] - m1n);
            float p3 = __expf(sacc[nt][3] - m1n);
            sacc[nt][0] = p0; sacc[nt][1] = p1;
            sacc[nt][2] = p2; sacc[nt][3] = p3;
            s0 += p0 + p1; s1 += p2 + p3;
        }
        #pragma unroll
        for (int o = 1; o <= 2; o <<= 1) {
            s0 += __shfl_xor_sync(0xffffffffu, s0, o);
            s1 += __shfl_xor_sync(0xffffffffu, s1, o);
        }
        l0 = l0 * f0 + s0;
        l1 = l1 * f1 + s1;
        #pragma unroll
        for (int d = 0; d < 8; d++) {
            oacc[d][0] *= f0; oacc[d][1] *= f0;
            oacc[d][2] *= f1; oacc[d][3] *= f1;
        }

        #pragma unroll
        for (int kcp = 0; kcp < 4; kcp++) {
            uint32_t pa_h[4], pa_l[4];
            #pragma unroll
            for (int t = 0; t < 2; t++) {
                int nt = 2 * kcp + t;
                float v0 = sacc[nt][0], v1 = sacc[nt][1];
                float v2 = sacc[nt][2], v3 = sacc[nt][3];
                uint32_t hp0 = pack_bf16(v0, v1);
                uint32_t hp1 = pack_bf16(v2, v3);
                __nv_bfloat162 hb0 = *reinterpret_cast<__nv_bfloat162*>(&hp0);
                __nv_bfloat162 hb1 = *reinterpret_cast<__nv_bfloat162*>(&hp1);
                pa_h[2 * t + 0] = hp0;
                pa_h[2 * t + 1] = hp1;
                pa_l[2 * t + 0] = pack_bf16(v0 - __bfloat162float(hb0.x),
                                            v1 - __bfloat162float(hb0.y));
                pa_l[2 * t + 1] = pack_bf16(v2 - __bfloat162float(hb1.x),
                                            v3 - __bfloat162float(hb1.y));
            }
            #pragma unroll
            for (int dp = 0; dp < 4; dp++) {
                uint32_t vh[4], vl[4];
                uint32_t off = swz((uint32_t)((kcp * 16 + (lane & 15)) * 128)
                                   + (dp * 16 + (lane >> 4) * 8) * 2);
                ldsm_x4t(vh, st + AV_HI + off);
                ldsm_x4t(vl, st + AV_LO + off);
                mma_bf16(oacc[2 * dp + 0], pa_h, vh[0], vh[1]);
                mma_bf16(oacc[2 * dp + 1], pa_h, vh[2], vh[3]);
                mma_bf16(oacc[2 * dp + 0], pa_l, vh[0], vh[1]);
                mma_bf16(oacc[2 * dp + 1], pa_l, vh[2], vh[3]);
                mma_bf16(oacc[2 * dp + 0], pa_h, vl[0], vl[1]);
                mma_bf16(oacc[2 * dp + 1], pa_h, vl[2], vl[3]);
            }
        }
    }

    const float inv0 = 1.f / l0;
    const float inv1 = 1.f / l1;
    __syncthreads();
    #pragma unroll
    for (int dt = 0; dt < 8; dt++) {
        #pragma unroll
        for (int half = 0; half < 2; half++) {
            int r = wid * 16 + (lane >> 2) + half * 8;
            int c = (lane & 3) * 2 + dt * 8;
            float inv = half ? inv1 : inv0;
            float v0 = oacc[dt][2 * half + 0] * inv;
            float v1 = oacc[dt][2 * half + 1] * inv;
            uint32_t hp = pack_bf16(v0, v1);
            __nv_bfloat162 hb = *reinterpret_cast<__nv_bfloat162*>(&hp);
            uint32_t lp = pack_bf16(v0 - __bfloat162float(hb.x),
                                    v1 - __bfloat162float(hb.y));
            *reinterpret_cast<uint32_t*>(asmem + r * AEPIT + c * 2) = hp;
            *reinterpret_cast<uint32_t*>(asmem + AEARR + r * AEPIT + c * 2) = lp;
        }
    }
    __syncthreads();
    #pragma unroll
    for (int it = 0; it < 4; it++) {
        int idx = tid + it * 256;
        int r = idx >> 3, ch = idx & 7;
        uint4 v = *reinterpret_cast<const uint4*>(asmem + r * AEPIT + ch * 16);
        uint4 w = *reinterpret_cast<const uint4*>(asmem + AEARR + r * AEPIT + ch * 16);
        size_t g = (size_t)(b * 128 + r) * 1024 + h * 64 + ch * 8;
        *reinterpret_cast<uint4*>(g_athi + g) = v;
        *reinterpret_cast<uint4*>(g_atlo + g) = w;
    }
}

// ---------------------------------------------------------------------------
// Launch
// ---------------------------------------------------------------------------
extern "C" void kernel_launch(void* const* d_in, const int* in_sizes, int n_in,
                              void* d_out, int out_size)
{
    const float* q   = (const float*)d_in[0];
    const float* kv  = (const float*)d_in[1];
    const float* Wq  = (const float*)d_in[2];
    const float* Wkv = (const float*)d_in[3];
    const float* Wo  = (const float*)d_in[4];
    const float* bo  = (const float*)d_in[5];
    float* out = (float*)d_out;

    cudaFuncSetAttribute(gemm12_kernel,
                         cudaFuncAttributeMaxDynamicSharedMemorySize, GEMM_SMEM);
    cudaFuncSetAttribute(gemm3_kernel,
                         cudaFuncAttributeMaxDynamicSharedMemorySize, GEMM_SMEM);
    cudaFuncSetAttribute(attn_mma_kernel,
                         cudaFuncAttributeMaxDynamicSharedMemorySize, ATT_SMEM);

    // 1) prep: splits + tiled transpose-splits
    prep_kernel<<<13824, 256>>>(q, kv, Wq, Wkv, Wo);

    // 2) fused query+kv projections -> bf16 hi/lo (Q pre-scaled by 1/8)
    gemm12_kernel<<<4608, 128, GEMM_SMEM>>>();

    // 3) flash attention (HMMA) -> bf16 hi/lo
    attn_mma_kernel<<<B_ASSETS * NH, 256, ATT_SMEM>>>();

    // 4) out = attn @ Wo + bo (fp32, staged epilogue)
    gemm3_kernel<<<dim3(QD / BN, 8192 / BM), 128, GEMM_SMEM>>>(out, bo);
}

// round 12
// speedup vs baseline: 1.0780x; 1.0051x over previous
#include <cuda_runtime.h>
#include <cuda_bf16.h>
#include <cstdint>
#include <math.h>

// ---------------------------------------------------------------------------
//   q (64,128,512)  kv (64,512,256)  Wq (512,1024)  Wkv (256,2048)
//   Wo (1024,512)  bo (512)  out (64,128,512)
// HMMA everywhere, fp32 via bf16 hi/lo 3-split. R9 scheduling. Softmax runs
// in log2 domain: Q pre-scaled by 0.125*log2(e) in GEMM1 epilogue, attention
// uses raw ex2.approx (no per-element FMUL).
// ---------------------------------------------------------------------------

#define B_ASSETS 64
#define I_LAT    128
#define J_WIN    512
#define QD       512
#define KVD      256
#define HID      1024
#define NH       16
#define HD       64

// ------------------------- scratch (no cudaMalloc) -------------------------
__device__ __nv_bfloat16  g_qhi  [8192u  * 512u],  g_qlo  [8192u  * 512u];
__device__ __nv_bfloat16  g_kvhi [32768u * 256u],  g_kvlo [32768u * 256u];
__device__ __nv_bfloat16  g_qphi [8192u  * 1024u], g_qplo [8192u  * 1024u];
__device__ __nv_bfloat16  g_kvphi[32768u * 2048u], g_kvplo[32768u * 2048u];
__device__ __nv_bfloat16  g_athi [8192u  * 1024u], g_atlo [8192u  * 1024u];
__device__ __nv_bfloat16  g_wqthi [1024u * 512u],  g_wqtlo [1024u * 512u];
__device__ __nv_bfloat16  g_wkvthi[2048u * 256u],  g_wkvtlo[2048u * 256u];
__device__ __nv_bfloat16  g_wothi [512u * 1024u],  g_wotlo [512u * 1024u];

// ------------------------------ PTX helpers --------------------------------
__device__ __forceinline__ uint32_t smem_u32(const void* p) {
    uint32_t a;
    asm("{ .reg .u64 t; cvta.to.shared.u64 t, %1; cvt.u32.u64 %0, t; }"
        : "=r"(a) : "l"(p));
    return a;
}
__device__ __forceinline__ void cp16(uint32_t dst, const void* src) {
    asm volatile("cp.async.cg.shared.global [%0], [%1], 16;"
                 :: "r"(dst), "l"(src));
}
#define CP_COMMIT() asm volatile("cp.async.commit_group;" ::: "memory")
#define CP_WAIT(n)  asm volatile("cp.async.wait_group %0;" :: "n"(n) : "memory")

__device__ __forceinline__ void ldsm_x4(uint32_t (&r)[4], uint32_t addr) {
    asm volatile("ldmatrix.sync.aligned.m8n8.x4.shared.b16 {%0,%1,%2,%3}, [%4];"
                 : "=r"(r[0]), "=r"(r[1]), "=r"(r[2]), "=r"(r[3]) : "r"(addr));
}
__device__ __forceinline__ void ldsm_x4t(uint32_t (&r)[4], uint32_t addr) {
    asm volatile("ldmatrix.sync.aligned.m8n8.x4.trans.shared.b16 {%0,%1,%2,%3}, [%4];"
                 : "=r"(r[0]), "=r"(r[1]), "=r"(r[2]), "=r"(r[3]) : "r"(addr));
}
__device__ __forceinline__ void mma_bf16(float (&d)[4],
                                         const uint32_t (&a)[4],
                                         uint32_t b0, uint32_t b1) {
    asm volatile(
        "mma.sync.aligned.m16n8k16.row.col.f32.bf16.bf16.f32 "
        "{%0,%1,%2,%3}, {%4,%5,%6,%7}, {%8,%9}, {%0,%1,%2,%3};"
        : "+f"(d[0]), "+f"(d[1]), "+f"(d[2]), "+f"(d[3])
        : "r"(a[0]), "r"(a[1]), "r"(a[2]), "r"(a[3]), "r"(b0), "r"(b1));
}
__device__ __forceinline__ float ex2(float x) {
    float y;
    asm("ex2.approx.f32 %0, %1;" : "=f"(y) : "f"(x));
    return y;
}
__device__ __forceinline__ uint32_t pack_bf16(float lo, float hi) {
    __nv_bfloat162 h = __floats2bfloat162_rn(lo, hi);
    return *reinterpret_cast<uint32_t*>(&h);
}
__device__ __forceinline__ uint32_t swz(uint32_t b) {
    return b ^ ((b >> 3) & 0x70);
}

// ---------------------------------------------------------------------------
// GEMM machinery: CTA 128x128 (128 threads, 4 warps, 2x2 of 64x64 tiles),
// BK=32, 3-stage cp.async, swizzled smem.
// ---------------------------------------------------------------------------
#define BM 128
#define BN 128
#define BK 32
#define ARR_B 8192u
#define STG_B 32768u
#define GEMM_SMEM (3 * 32768)
#define EPIT   272u
#define EARR   34816u
#define EPIT32 528u

__device__ __forceinline__ void gemm_mainloop(
    const __nv_bfloat16* __restrict__ Ahi, const __nv_bfloat16* __restrict__ Alo,
    const __nv_bfloat16* __restrict__ Bthi, const __nv_bfloat16* __restrict__ Btlo,
    int K, int m0, int n0, uint32_t sbase, float (&acc)[4][8][4])
{
    const int tid  = threadIdx.x;
    const int wid  = tid >> 5;
    const int lane = tid & 31;
    const int wm = (wid >> 1) * 64;
    const int wn = (wid & 1) * 64;

    auto load_stage = [&](int s, int kbase) {
        uint32_t st = sbase + (uint32_t)s * STG_B;
        #pragma unroll
        for (int it = 0; it < 4; it++) {
            int c   = tid + it * 128;
            int row = c >> 2;
            int ch  = c & 3;
            uint32_t so = st + swz((uint32_t)(row * 64 + ch * 16));
            size_t goa = (size_t)(m0 + row) * K + kbase + ch * 8;
            size_t gob = (size_t)(n0 + row) * K + kbase + ch * 8;
            cp16(so + 0 * ARR_B, Ahi  + goa);
            cp16(so + 1 * ARR_B, Alo  + goa);
            cp16(so + 2 * ARR_B, Bthi + gob);
            cp16(so + 3 * ARR_B, Btlo + gob);
        }
    };

    #pragma unroll
    for (int i = 0; i < 4; i++)
        #pragma unroll
        for (int j = 0; j < 8; j++)
            #pragma unroll
            for (int v = 0; v < 4; v++) acc[i][j][v] = 0.f;

    const int nk = K / BK;
    load_stage(0, 0);
    CP_COMMIT();
    load_stage(1, BK);
    CP_COMMIT();

    const int a_row = lane & 15;
    const int a_k8  = (lane >> 4) * 8;
    const int b_row = (lane & 7) + ((lane >> 4) << 3);
    const int b_k8  = ((lane >> 3) & 1) * 8;

    int s_cur = 0, s_nxt = 2;
    for (int kc = 0; kc < nk; kc++) {
        if (kc < nk - 1) { CP_WAIT(1); } else { CP_WAIT(0); }
        __syncthreads();
        if (kc + 2 < nk) {
            load_stage(s_nxt, (kc + 2) * BK);
            CP_COMMIT();
        }
        const uint32_t stg = sbase + (uint32_t)s_cur * STG_B;

        #pragma unroll
        for (int k16 = 0; k16 < BK; k16 += 16) {
            uint32_t ah[4][4], al[4][4];
            #pragma unroll
            for (int mt = 0; mt < 4; mt++) {
                uint32_t off = swz((uint32_t)((wm + mt * 16 + a_row) * 64)
                                   + (k16 + a_k8) * 2);
                ldsm_x4(ah[mt], stg + off);
                ldsm_x4(al[mt], stg + 1 * ARR_B + off);
            }
            #pragma unroll
            for (int p = 0; p < 4; p++) {
                uint32_t bh[4], bl[4];
                uint32_t off = swz((uint32_t)((wn + p * 16 + b_row) * 64)
                                   + (k16 + b_k8) * 2);
                ldsm_x4(bh, stg + 2 * ARR_B + off);
                ldsm_x4(bl, stg + 3 * ARR_B + off);
                #pragma unroll
                for (int mt = 0; mt < 4; mt++) {
                    mma_bf16(acc[mt][2 * p + 0], ah[mt], bh[0], bh[1]);
                    mma_bf16(acc[mt][2 * p + 1], ah[mt], bh[2], bh[3]);
                }
                #pragma unroll
                for (int mt = 0; mt < 4; mt++) {
                    mma_bf16(acc[mt][2 * p + 0], ah[mt], bl[0], bl[1]);
                    mma_bf16(acc[mt][2 * p + 1], ah[mt], bl[2], bl[3]);
                }
                #pragma unroll
                for (int mt = 0; mt < 4; mt++) {
                    mma_bf16(acc[mt][2 * p + 0], al[mt], bh[0], bh[1]);
                    mma_bf16(acc[mt][2 * p + 1], al[mt], bh[2], bh[3]);
                }
            }
        }
        s_cur = (s_cur + 1 == 3) ? 0 : s_cur + 1;
        s_nxt = (s_nxt + 1 == 3) ? 0 : s_nxt + 1;
    }
}

// ---------------------------------------------------------------------------
// Fused GEMM1 + GEMM2: blocks [0,512) query proj (pre-scaled by
// 0.125*log2(e) for log2-domain softmax), blocks [512,4608) kv proj.
// ---------------------------------------------------------------------------
__global__ __launch_bounds__(128, 2) void gemm12_kernel()
{
    extern __shared__ __nv_bfloat16 smem[];
    char* smc = reinterpret_cast<char*>(smem);
    const uint32_t sbase = smem_u32(smem);
    const int tid  = threadIdx.x;
    const int wid  = tid >> 5;
    const int lane = tid & 31;

    const int bid = blockIdx.x;
    const bool g1 = bid < 512;
    const __nv_bfloat16* Ahi  = g1 ? g_qhi   : g_kvhi;
    const __nv_bfloat16* Alo  = g1 ? g_qlo   : g_kvlo;
    const __nv_bfloat16* Bthi = g1 ? g_wqthi : g_wkvthi;
    const __nv_bfloat16* Btlo = g1 ? g_wqtlo : g_wkvtlo;
    __nv_bfloat16* Chi = g1 ? g_qphi : g_kvphi;
    __nv_bfloat16* Clo = g1 ? g_qplo : g_kvplo;
    const int K = g1 ? QD : KVD;
    const int N = g1 ? HID : 2 * HID;
    const int nbx = g1 ? 8 : 16;
    const int lb  = g1 ? bid : bid - 512;
    const int m0 = (lb / nbx) * BM;
    const int n0 = (lb % nbx) * BN;
    // 0.125 * log2(e): scores come out in log2 units for ex2-based softmax
    const float oscale = g1 ? 0.18033688011112042f : 1.0f;

    float acc[4][8][4];
    gemm_mainloop(Ahi, Alo, Bthi, Btlo, K, m0, n0, sbase, acc);

    const int wm = (wid >> 1) * 64;
    const int wn = (wid & 1) * 64;
    const int er = lane >> 2;
    const int ec = (lane & 3) * 2;
    __syncthreads();
    #pragma unroll
    for (int mt = 0; mt < 4; mt++) {
        #pragma unroll
        for (int nt = 0; nt < 8; nt++) {
            #pragma unroll
            for (int half = 0; half < 2; half++) {
                int r = wm + mt * 16 + er + half * 8;
                int c = wn + nt * 8 + ec;
                float v0 = acc[mt][nt][2 * half + 0] * oscale;
                float v1 = acc[mt][nt][2 * half + 1] * oscale;
                uint32_t hp = pack_bf16(v0, v1);
                __nv_bfloat162 hb = *reinterpret_cast<__nv_bfloat162*>(&hp);
                uint32_t lp = pack_bf16(v0 - __bfloat162float(hb.x),
                                        v1 - __bfloat162float(hb.y));
                *reinterpret_cast<uint32_t*>(smc + r * EPIT + c * 2) = hp;
                *reinterpret_cast<uint32_t*>(smc + EARR + r * EPIT + c * 2) = lp;
            }
        }
    }
    __syncthreads();
    #pragma unroll
    for (int it = 0; it < 16; it++) {
        int idx = tid + it * 128;
        int r = idx >> 4, ch = idx & 15;
        uint4 v = *reinterpret_cast<const uint4*>(smc + r * EPIT + ch * 16);
        uint4 w = *reinterpret_cast<const uint4*>(smc + EARR + r * EPIT + ch * 16);
        size_t g = (size_t)(m0 + r) * N + n0 + ch * 8;
        *reinterpret_cast<uint4*>(Chi + g) = v;
        *reinterpret_cast<uint4*>(Clo + g) = w;
    }
}

// ---------------------------------------------------------------------------
// GEMM3: out = attn @ Wo + bo (fp32, smem-staged epilogue)
// ---------------------------------------------------------------------------
__global__ __launch_bounds__(128, 2) void gemm3_kernel(
    float* __restrict__ C, const float* __restrict__ bias)
{
    extern __shared__ __nv_bfloat16 smem[];
    char* smc = reinterpret_cast<char*>(smem);
    const uint32_t sbase = smem_u32(smem);
    const int tid  = threadIdx.x;
    const int wid  = tid >> 5;
    const int lane = tid & 31;
    const int m0 = blockIdx.y * BM;
    const int n0 = blockIdx.x * BN;
    const int N = QD;

    float acc[4][8][4];
    gemm_mainloop(g_athi, g_atlo, g_wothi, g_wotlo, HID, m0, n0, sbase, acc);

    const int wm = (wid >> 1) * 64;
    const int wn = (wid & 1) * 64;
    const int er = lane >> 2;
    const int ec = (lane & 3) * 2;
    __syncthreads();
    #pragma unroll
    for (int mt = 0; mt < 4; mt++) {
        #pragma unroll
        for (int nt = 0; nt < 8; nt++) {
            #pragma unroll
            for (int half = 0; half < 2; half++) {
                int r = wm + mt * 16 + er + half * 8;
                int c = wn + nt * 8 + ec;
                float2 v = make_float2(acc[mt][nt][2 * half + 0],
                                       acc[mt][nt][2 * half + 1]);
                *reinterpret_cast<float2*>(smc + r * EPIT32 + c * 4) = v;
            }
        }
    }
    __syncthreads();
    #pragma unroll
    for (int it = 0; it < 32; it++) {
        int idx = tid + it * 128;
        int r = idx >> 5, ch = idx & 31;
        float4 v = *reinterpret_cast<const float4*>(smc + r * EPIT32 + ch * 16);
        float4 bv = *reinterpret_cast<const float4*>(bias + n0 + ch * 4);
        v.x += bv.x; v.y += bv.y; v.z += bv.z; v.w += bv.w;
        *reinterpret_cast<float4*>(C + (size_t)(m0 + r) * N + n0 + ch * 4) = v;
    }
}

// ---------------------------------------------------------------------------
// Prep: blocks [0,12288) splits; [12288,13824) smem-tiled transpose-splits.
// ---------------------------------------------------------------------------
__global__ __launch_bounds__(256) void prep_kernel(
    const float* __restrict__ q,   const float* __restrict__ kv,
    const float* __restrict__ Wq,  const float* __restrict__ Wkv,
    const float* __restrict__ Wo)
{
    const int tid = threadIdx.x;
    if (blockIdx.x < 12288) {
        int i = blockIdx.x * 256 + tid;
        const float* src; __nv_bfloat16 *hi, *lo; int base;
        if (i < 1048576) { src = q;  hi = g_qhi;  lo = g_qlo;  base = i; }
        else             { src = kv; hi = g_kvhi; lo = g_kvlo; base = i - 1048576; }
        float4 v = reinterpret_cast<const float4*>(src)[base];
        __nv_bfloat162 hp0 = __floats2bfloat162_rn(v.x, v.y);
        __nv_bfloat162 hp1 = __floats2bfloat162_rn(v.z, v.w);
        __nv_bfloat162 lp0 = __floats2bfloat162_rn(v.x - __bfloat162float(hp0.x),
                                                   v.y - __bfloat162float(hp0.y));
        __nv_bfloat162 lp1 = __floats2bfloat162_rn(v.z - __bfloat162float(hp1.x),
                                                   v.w - __bfloat162float(hp1.y));
        reinterpret_cast<__nv_bfloat162*>(hi)[2 * base + 0] = hp0;
        reinterpret_cast<__nv_bfloat162*>(hi)[2 * base + 1] = hp1;
        reinterpret_cast<__nv_bfloat162*>(lo)[2 * base + 0] = lp0;
        reinterpret_cast<__nv_bfloat162*>(lo)[2 * base + 1] = lp1;
        return;
    }

    __shared__ __nv_bfloat16 sh_hi[32][36];
    __shared__ __nv_bfloat16 sh_lo[32][36];

    int bt = blockIdx.x - 12288;
    const float* W; __nv_bfloat16 *Whi, *Wlo; int K, N, tn_cnt;
    if (bt < 512)       { W = Wq;  Whi = g_wqthi;  Wlo = g_wqtlo;  K = 512;  N = 1024; tn_cnt = 32; }
    else if (bt < 1024) { W = Wkv; Whi = g_wkvthi; Wlo = g_wkvtlo; K = 256;  N = 2048; tn_cnt = 64; bt -= 512; }
    else                { W = Wo;  Whi = g_wothi;  Wlo = g_wotlo;  K = 1024; N = 512;  tn_cnt = 16; bt -= 1024; }
    const int k0 = (bt / tn_cnt) * 32;
    const int n0 = (bt % tn_cnt) * 32;

    {
        int r  = tid >> 3;
        int c4 = (tid & 7) << 2;
        float4 v = *reinterpret_cast<const float4*>(
            W + (size_t)(k0 + r) * N + n0 + c4);
        float vv[4] = { v.x, v.y, v.z, v.w };
        #pragma unroll
        for (int i = 0; i < 4; i++) {
            __nv_bfloat16 h = __float2bfloat16_rn(vv[i]);
            sh_hi[c4 + i][r] = h;
            sh_lo[c4 + i][r] = __float2bfloat16_rn(vv[i] - __bfloat162float(h));
        }
    }
    __syncthreads();
    {
        int nl = tid >> 3;
        int k4 = (tid & 7) << 2;
        uint32_t h0 = pack_bf16(__bfloat162float(sh_hi[nl][k4 + 0]),
                                __bfloat162float(sh_hi[nl][k4 + 1]));
        uint32_t h1 = pack_bf16(__bfloat162float(sh_hi[nl][k4 + 2]),
                                __bfloat162float(sh_hi[nl][k4 + 3]));
        uint32_t l0 = pack_bf16(__bfloat162float(sh_lo[nl][k4 + 0]),
                                __bfloat162float(sh_lo[nl][k4 + 1]));
        uint32_t l1 = pack_bf16(__bfloat162float(sh_lo[nl][k4 + 2]),
                                __bfloat162float(sh_lo[nl][k4 + 3]));
        *reinterpret_cast<uint2*>(Whi + (size_t)(n0 + nl) * K + k0 + k4) =
            make_uint2(h0, h1);
        *reinterpret_cast<uint2*>(Wlo + (size_t)(n0 + nl) * K + k0 + k4) =
            make_uint2(l0, l1);
    }
}

// ---------------------------------------------------------------------------
// HMMA flash attention: CTA = (b, h), 8 warps x 16 rows; single barrier per
// jt; S is in log2 units (Q pre-scaled), softmax uses ex2.approx directly.
// ---------------------------------------------------------------------------
#define AQ_HI 0u
#define AQ_LO 16384u
#define ASTG  32768u
#define AST_SZ 32768u
#define AK_HI 0u
#define AK_LO 8192u
#define AV_HI 16384u
#define AV_LO 24576u
#define ATT_SMEM (32768 + 2 * 32768)
#define AEPIT 144u
#define AEARR 18432u

__global__ __launch_bounds__(256, 2) void attn_mma_kernel()
{
    extern __shared__ char asmem[];
    const uint32_t sbase = smem_u32(asmem);
    const int b = blockIdx.x >> 4;
    const int h = blockIdx.x & 15;
    const int tid  = threadIdx.x;
    const int wid  = tid >> 5;
    const int lane = tid & 31;

    for (int c = tid; c < 1024; c += 256) {
        int row = c >> 3, ch = c & 7;
        uint32_t so = swz((uint32_t)(row * 128 + ch * 16));
        size_t g = (size_t)(b * 128 + row) * 1024 + h * 64 + ch * 8;
        *reinterpret_cast<uint4*>(asmem + AQ_HI + so) =
            *reinterpret_cast<const uint4*>(g_qphi + g);
        *reinterpret_cast<uint4*>(asmem + AQ_LO + so) =
            *reinterpret_cast<const uint4*>(g_qplo + g);
    }

    auto load_kv = [&](int jt, int s) {
        uint32_t st = sbase + ASTG + (uint32_t)s * AST_SZ;
        #pragma unroll
        for (int half = 0; half < 2; half++) {
            int c = tid + half * 256;
            int row = c >> 3, ch = c & 7;
            uint32_t so = swz((uint32_t)(row * 128 + ch * 16));
            size_t kr = (size_t)(b * J_WIN + jt * 64 + row) * 2048 + h * 64 + ch * 8;
            cp16(st + AK_HI + so, g_kvphi + kr);
            cp16(st + AK_LO + so, g_kvplo + kr);
            cp16(st + AV_HI + so, g_kvphi + kr + 1024);
            cp16(st + AV_LO + so, g_kvplo + kr + 1024);
        }
    };

    load_kv(0, 0);
    CP_COMMIT();

    const int a_row = lane & 15;
    const int a_k8  = (lane >> 4) * 8;
    const int b_row = (lane & 7) + ((lane >> 4) << 3);
    const int b_k8  = ((lane >> 3) & 1) * 8;

    __syncthreads();
    uint32_t qah[4][4], qal[4][4];
    #pragma unroll
    for (int kc = 0; kc < 4; kc++) {
        uint32_t off = swz((uint32_t)((wid * 16 + a_row) * 128)
                           + (kc * 16 + a_k8) * 2);
        ldsm_x4(qah[kc], sbase + AQ_HI + off);
        ldsm_x4(qal[kc], sbase + AQ_LO + off);
    }

    float oacc[8][4];
    #pragma unroll
    for (int d = 0; d < 8; d++)
        #pragma unroll
        for (int v = 0; v < 4; v++) oacc[d][v] = 0.f;
    float m0 = -INFINITY, m1 = -INFINITY, l0 = 0.f, l1 = 0.f;

    for (int jt = 0; jt < 8; jt++) {
        CP_WAIT(0);
        __syncthreads();
        if (jt + 1 < 8) {
            load_kv(jt + 1, (jt + 1) & 1);
            CP_COMMIT();
        }
        const uint32_t st = sbase + ASTG + (uint32_t)(jt & 1) * AST_SZ;

        float sacc[8][4];
        #pragma unroll
        for (int p = 0; p < 8; p++)
            #pragma unroll
            for (int v = 0; v < 4; v++) sacc[p][v] = 0.f;

        #pragma unroll
        for (int kc = 0; kc < 4; kc++) {
            #pragma unroll
            for (int p = 0; p < 4; p++) {
                uint32_t bh[4], bl[4];
                uint32_t off = swz((uint32_t)((p * 16 + b_row) * 128)
                                   + (kc * 16 + b_k8) * 2);
                ldsm_x4(bh, st + AK_HI + off);
                ldsm_x4(bl, st + AK_LO + off);
                mma_bf16(sacc[2 * p + 0], qah[kc], bh[0], bh[1]);
                mma_bf16(sacc[2 * p + 1], qah[kc], bh[2], bh[3]);
                mma_bf16(sacc[2 * p + 0], qah[kc], bl[0], bl[1]);
                mma_bf16(sacc[2 * p + 1], qah[kc], bl[2], bl[3]);
                mma_bf16(sacc[2 * p + 0], qal[kc], bh[0], bh[1]);
                mma_bf16(sacc[2 * p + 1], qal[kc], bh[2], bh[3]);
            }
        }

        // ---- online softmax in log2 domain (ex2.approx, no FMULs) ----
        float mx0 = -INFINITY, mx1 = -INFINITY;
        #pragma unroll
        for (int nt = 0; nt < 8; nt++) {
            mx0 = fmaxf(mx0, fmaxf(sacc[nt][0], sacc[nt][1]));
            mx1 = fmaxf(mx1, fmaxf(sacc[nt][2], sacc[nt][3]));
        }
        #pragma unroll
        for (int o = 1; o <= 2; o <<= 1) {
            mx0 = fmaxf(mx0, __shfl_xor_sync(0xffffffffu, mx0, o));
            mx1 = fmaxf(mx1, __shfl_xor_sync(0xffffffffu, mx1, o));
        }
        float m0n = fmaxf(m0, mx0);
        float m1n = fmaxf(m1, mx1);
        float f0 = ex2(m0 - m0n);
        float f1 = ex2(m1 - m1n);
        m0 = m0n; m1 = m1n;

        float s0 = 0.f, s1 = 0.f;
        #pragma unroll
        for (int nt = 0; nt < 8; nt++) {
            float p0 = ex2(sacc[nt][0] - m0n);
            float p1 = ex2(sacc[nt][1] - m0n);
            float p2 = ex2(sacc[nt][2] - m1n);
            float p3 = ex2(sacc[nt][3] - m1n);
            sacc[nt][0] = p0; sacc[nt][1] = p1;
            sacc[nt][2] = p2; sacc[nt][3] = p3;
            s0 += p0 + p1; s1 += p2 + p3;
        }
        #pragma unroll
        for (int o = 1; o <= 2; o <<= 1) {
            s0 += __shfl_xor_sync(0xffffffffu, s0, o);
            s1 += __shfl_xor_sync(0xffffffffu, s1, o);
        }
        l0 = l0 * f0 + s0;
        l1 = l1 * f1 + s1;
        #pragma unroll
        for (int d = 0; d < 8; d++) {
            oacc[d][0] *= f0; oacc[d][1] *= f0;
            oacc[d][2] *= f1; oacc[d][3] *= f1;
        }

        #pragma unroll
        for (int kcp = 0; kcp < 4; kcp++) {
            uint32_t pa_h[4], pa_l[4];
            #pragma unroll
            for (int t = 0; t < 2; t++) {
                int nt = 2 * kcp + t;
                float v0 = sacc[nt][0], v1 = sacc[nt][1];
                float v2 = sacc[nt][2], v3 = sacc[nt][3];
                uint32_t hp0 = pack_bf16(v0, v1);
                uint32_t hp1 = pack_bf16(v2, v3);
                __nv_bfloat162 hb0 = *reinterpret_cast<__nv_bfloat162*>(&hp0);
                __nv_bfloat162 hb1 = *reinterpret_cast<__nv_bfloat162*>(&hp1);
                pa_h[2 * t + 0] = hp0;
                pa_h[2 * t + 1] = hp1;
                pa_l[2 * t + 0] = pack_bf16(v0 - __bfloat162float(hb0.x),
                                            v1 - __bfloat162float(hb0.y));
                pa_l[2 * t + 1] = pack_bf16(v2 - __bfloat162float(hb1.x),
                                            v3 - __bfloat162float(hb1.y));
            }
            #pragma unroll
            for (int dp = 0; dp < 4; dp++) {
                uint32_t vh[4], vl[4];
                uint32_t off = swz((uint32_t)((kcp * 16 + (lane & 15)) * 128)
                                   + (dp * 16 + (lane >> 4) * 8) * 2);
                ldsm_x4t(vh, st + AV_HI + off);
                ldsm_x4t(vl, st + AV_LO + off);
                mma_bf16(oacc[2 * dp + 0], pa_h, vh[0], vh[1]);
                mma_bf16(oacc[2 * dp + 1], pa_h, vh[2], vh[3]);
                mma_bf16(oacc[2 * dp + 0], pa_l, vh[0], vh[1]);
                mma_bf16(oacc[2 * dp + 1], pa_l, vh[2], vh[3]);
                mma_bf16(oacc[2 * dp + 0], pa_h, vl[0], vl[1]);
                mma_bf16(oacc[2 * dp + 1], pa_h, vl[2], vl[3]);
            }
        }
    }

    const float inv0 = 1.f / l0;
    const float inv1 = 1.f / l1;
    __syncthreads();
    #pragma unroll
    for (int dt = 0; dt < 8; dt++) {
        #pragma unroll
        for (int half = 0; half < 2; half++) {
            int r = wid * 16 + (lane >> 2) + half * 8;
            int c = (lane & 3) * 2 + dt * 8;
            float inv = half ? inv1 : inv0;
            float v0 = oacc[dt][2 * half + 0] * inv;
            float v1 = oacc[dt][2 * half + 1] * inv;
            uint32_t hp = pack_bf16(v0, v1);
            __nv_bfloat162 hb = *reinterpret_cast<__nv_bfloat162*>(&hp);
            uint32_t lp = pack_bf16(v0 - __bfloat162float(hb.x),
                                    v1 - __bfloat162float(hb.y));
            *reinterpret_cast<uint32_t*>(asmem + r * AEPIT + c * 2) = hp;
            *reinterpret_cast<uint32_t*>(asmem + AEARR + r * AEPIT + c * 2) = lp;
        }
    }
    __syncthreads();
    #pragma unroll
    for (int it = 0; it < 4; it++) {
        int idx = tid + it * 256;
        int r = idx >> 3, ch = idx & 7;
        uint4 v = *reinterpret_cast<const uint4*>(asmem + r * AEPIT + ch * 16);
        uint4 w = *reinterpret_cast<const uint4*>(asmem + AEARR + r * AEPIT + ch * 16);
        size_t g = (size_t)(b * 128 + r) * 1024 + h * 64 + ch * 8;
        *reinterpret_cast<uint4*>(g_athi + g) = v;
        *reinterpret_cast<uint4*>(g_atlo + g) = w;
    }
}

// ---------------------------------------------------------------------------
// Launch
// ---------------------------------------------------------------------------
extern "C" void kernel_launch(void* const* d_in, const int* in_sizes, int n_in,
                              void* d_out, int out_size)
{
    const float* q   = (const float*)d_in[0];
    const float* kv  = (const float*)d_in[1];
    const float* Wq  = (const float*)d_in[2];
    const float* Wkv = (const float*)d_in[3];
    const float* Wo  = (const float*)d_in[4];
    const float* bo  = (const float*)d_in[5];
    float* out = (float*)d_out;

    cudaFuncSetAttribute(gemm12_kernel,
                         cudaFuncAttributeMaxDynamicSharedMemorySize, GEMM_SMEM);
    cudaFuncSetAttribute(gemm3_kernel,
                         cudaFuncAttributeMaxDynamicSharedMemorySize, GEMM_SMEM);
    cudaFuncSetAttribute(attn_mma_kernel,
                         cudaFuncAttributeMaxDynamicSharedMemorySize, ATT_SMEM);

    // 1) prep: splits + tiled transpose-splits
    prep_kernel<<<13824, 256>>>(q, kv, Wq, Wkv, Wo);

    // 2) fused query+kv projections -> bf16 hi/lo (Q pre-scaled, log2 domain)
    gemm12_kernel<<<4608, 128, GEMM_SMEM>>>();

    // 3) flash attention (HMMA, ex2-based softmax) -> bf16 hi/lo
    attn_mma_kernel<<<B_ASSETS * NH, 256, ATT_SMEM>>>();

    // 4) out = attn @ Wo + bo (fp32, staged epilogue)
    gemm3_kernel<<<dim3(QD / BN, 8192 / BM), 128, GEMM_SMEM>>>(out, bo);
}